// round 3
// baseline (speedup 1.0000x reference)
#include <cuda_runtime.h>
#include <cstdint>

#define EN 2048
#define IN_ 256
#define TN 256
#define BN 32
#define EW 64   // uint32 words of packed exc spikes per batch
#define IW 8    // uint32 words of packed inh spikes per batch

// persistent scratch (no allocation allowed)
__device__ __align__(16) uint32_t g_wrec_t[EW * EN]; // transposed packed w_rec
__device__ float g_rowsum[EN];    // popcount of w_rec row j (exact integer as float)
__device__ float g_cs_wie[EN];    // sum_i w_ie[i][e] (ascending i)
__device__ float g_cs_wei[IN_];   // sum_e w_ei[e][i] (ascending e)

// ---------------- prep kernels (deterministic, rerun every launch) ----------------
__global__ void prep_pack(const float* __restrict__ wrec) {
    int idx = blockIdx.x * blockDim.x + threadIdx.x;  // 0 .. EN*EW-1
    int j = idx >> 6, w = idx & 63;
    // w_rec entries are exactly 0.0f or 1.0f -> nonzero iff bit pattern nonzero
    const uint4* p = reinterpret_cast<const uint4*>(wrec + (size_t)j * EN + (size_t)w * 32);
    uint32_t m = 0;
#pragma unroll
    for (int k = 0; k < 8; k++) {
        uint4 f = p[k];
        m |= (f.x ? 1u : 0u) << (k * 4 + 0);
        m |= (f.y ? 1u : 0u) << (k * 4 + 1);
        m |= (f.z ? 1u : 0u) << (k * 4 + 2);
        m |= (f.w ? 1u : 0u) << (k * 4 + 3);
    }
    g_wrec_t[w * EN + j] = m;
}

__global__ void prep_sums(const float* __restrict__ wie, const float* __restrict__ wei) {
    int t = blockIdx.x * blockDim.x + threadIdx.x;  // 2048 threads
    if (t < EN) {
        int c = 0;
#pragma unroll 8
        for (int w = 0; w < EW; w++) c += __popc(g_wrec_t[w * EN + t]);
        g_rowsum[t] = (float)c;
        float s = 0.f;
        for (int i = 0; i < IN_; i++) s = __fadd_rn(s, wie[(size_t)i * EN + t]);
        g_cs_wie[t] = s;
    }
    if (t < IN_) {
        float s = 0.f;
        for (int e = 0; e < EN; e++) s = __fadd_rn(s, wei[(size_t)e * IN_ + t]);
        g_cs_wei[t] = s;
    }
}

// ---------------- main simulator: one CTA per batch, fully independent ----------------
__global__ __launch_bounds__(1024, 1)
void sim_kernel(const float* __restrict__ x,
                const float* __restrict__ wei,
                const float* __restrict__ wie,
                float* __restrict__ out)
{
    __shared__ uint32_t s_ez[2][EW];
    __shared__ uint32_t s_iz[2][IW];

    const int tid  = threadIdx.x;
    const int b    = blockIdx.x;
    const int e0   = tid, e1 = tid + 1024;
    const int warp = tid >> 5, lane = tid & 31;

    // register-resident state for the whole run
    float v0 = 0.f, i0 = 0.f, v1 = 0.f, i1 = 0.f;  // exc neurons e0, e1
    float iv = 0.f, ii = 0.f;                      // inh neuron tid (tid<256)

    // hoisted loop-invariant constants (off the per-step critical path)
    const float rs0  = g_rowsum[e0], rs1 = g_rowsum[e1];
    const float cw0  = g_cs_wie[e0], cw1 = g_cs_wie[e1];
    const float cwei = (tid < IN_) ? g_cs_wei[tid] : 0.f;

    if (tid < EW) { s_ez[0][tid] = 0u; s_ez[1][tid] = 0u; }
    if (tid < IW) { s_iz[0][tid] = 0u; s_iz[1][tid] = 0u; }
    __syncthreads();

    int prev_all = 0, prev_any = 0;   // classification of previous step's spikes

    float xn0 = x[(size_t)b * EN + e0];
    float xn1 = x[(size_t)b * EN + e1];
    float* op = out + (size_t)b * EN;

    for (int t = 0; t < TN; t++) {
        const int wp = t & 1, rp = wp ^ 1;

        // ---- [a] cross terms from previous step's spikes ----
        float rec0, rec1, inh0, inh1;
        if (prev_all)       { rec0 = rs0; rec1 = rs1; inh0 = cw0; inh1 = cw1; }
        else if (!prev_any) { rec0 = 0.f; rec1 = 0.f; inh0 = 0.f; inh1 = 0.f; }
        else {
            // exact: integer popcount for rec, ascending fadd for inh
            int c0 = 0, c1 = 0;
#pragma unroll 8
            for (int w = 0; w < EW; w++) {
                uint32_t ez = s_ez[rp][w];
                c0 += __popc(ez & g_wrec_t[w * EN + e0]);
                c1 += __popc(ez & g_wrec_t[w * EN + e1]);
            }
            rec0 = (float)c0; rec1 = (float)c1;
            inh0 = 0.f; inh1 = 0.f;
#pragma unroll
            for (int w = 0; w < IW; w++) {
                uint32_t m = s_iz[rp][w];
                while (m) {
                    int c = __ffs(m) - 1; m &= m - 1;
                    const float* wr = wie + (size_t)(w * 32 + c) * EN;
                    inh0 = __fadd_rn(inh0, wr[e0]);
                    inh1 = __fadd_rn(inh1, wr[e1]);
                }
            }
        }

        // ---- [b] excitatory update (JAX-exact rounding order) ----
        float id0 = __fadd_rn(i0, __fmul_rn(-0.2f, i0));
        float vd0 = __fadd_rn(v0, __fmul_rn(0.1f, __fadd_rn(__fsub_rn(0.f, v0), i0)));
        float id1 = __fadd_rn(i1, __fmul_rn(-0.2f, i1));
        float vd1 = __fadd_rn(v1, __fmul_rn(0.1f, __fadd_rn(__fsub_rn(0.f, v1), i1)));
        int z0 = __fsub_rn(vd0, 1.0f) > 0.f;
        int z1 = __fsub_rn(vd1, 1.0f) > 0.f;
        v0 = z0 ? 0.f : vd0;
        v1 = z1 ? 0.f : vd1;
        i0 = __fadd_rn(__fadd_rn(id0, __fsub_rn(xn0, inh0)), rec0);
        i1 = __fadd_rn(__fadd_rn(id1, __fsub_rn(xn1, inh1)), rec1);

        op[e0] = z0 ? 1.f : 0.f;
        op[e1] = z1 ? 1.f : 0.f;
        op += (size_t)BN * EN;

        // prefetch next step's input (latency hidden behind barriers)
        if (t + 1 < TN) {
            const float* xb = x + ((size_t)(t + 1) * BN + b) * EN;
            xn0 = xb[e0];
            xn1 = xb[e1];
        }

        // inhibitory decay + spike from OLD inh state (no dep on new ez)
        float ii_dec = __fadd_rn(ii, __fmul_rn(-0.2f, ii));
        float vi_dec = __fadd_rn(iv, __fmul_rn(0.1f, __fadd_rn(__fsub_rn(0.f, iv), ii)));
        int zi = __fsub_rn(vi_dec, 1.0f) > 0.f;   // tid>=256: state stays 0 -> zi=0
        iv = zi ? 0.f : vi_dec;

        // ---- [c] publish new spikes + classify via barrier reductions (no atomics) ----
        uint32_t eb0  = __ballot_sync(0xffffffffu, z0);
        uint32_t eb1  = __ballot_sync(0xffffffffu, z1);
        uint32_t ibal = __ballot_sync(0xffffffffu, zi);
        if (lane == 0) {
            s_ez[wp][warp]      = eb0;
            s_ez[wp][32 + warp] = eb1;
            if (warp < IW) s_iz[wp][warp] = ibal;
        }

        int allp = z0 && z1 && (tid >= IN_ || zi);
        int anyp = z0 || z1 || zi;
        int new_all = __syncthreads_and(allp);   // barrier 1 (orders [c] stores)
        int new_any = __syncthreads_or(anyp);    // barrier 2

        // ---- [d] inhibitory current update with NEW exc spikes ----
        if (tid < IN_) {
            float xi;
            if (new_all)       xi = cwei;
            else if (!new_any) xi = 0.f;
            else {
                xi = 0.f;
                for (int w = 0; w < EW; w++) {
                    uint32_t m = s_ez[wp][w];
                    while (m) {
                        int c = __ffs(m) - 1; m &= m - 1;
                        xi = __fadd_rn(xi, wei[(size_t)(w * 32 + c) * IN_ + tid]);
                    }
                }
            }
            ii = __fadd_rn(ii_dec, xi);
        }
        prev_all = new_all;
        prev_any = new_any;
        // next iteration's s_ez/s_iz writes target buffer rp, last read before
        // this iteration's barriers -> ordered by the two BAR.REDs above.
    }
}

extern "C" void kernel_launch(void* const* d_in, const int* in_sizes, int n_in,
                              void* d_out, int out_size)
{
    const float* x     = (const float*)d_in[0];  // [T,B,E]
    // d_in[1] = w_in (identity) -- exact pass-through, unused
    const float* w_rec = (const float*)d_in[2];  // [E,E]
    const float* w_ei  = (const float*)d_in[3];  // [E,I]
    const float* w_ie  = (const float*)d_in[4];  // [I,E]
    float* out = (float*)d_out;

    prep_pack<<<(EN * EW) / 256, 256>>>(w_rec);
    prep_sums<<<8, 256>>>(w_ie, w_ei);
    sim_kernel<<<BN, 1024>>>(x, w_ei, w_ie, out);
}

// round 4
// speedup vs baseline: 1.5012x; 1.5012x over previous
#include <cuda_runtime.h>
#include <cstdint>

#define EN 2048
#define IN_ 256
#define TN 256
#define BN 32
#define EWORDS 64   // uint32 words of packed exc spikes
#define IWORDS 8    // uint32 words of packed inh spikes
#define NT 512      // threads per CTA (4 exc neurons each, stride 512)

// persistent scratch (no allocation allowed)
__device__ __align__(16) uint32_t g_wrec_t[EWORDS * EN]; // transposed packed w_rec
__device__ float g_rowsum[EN];    // popcount of w_rec row j (exact integer as float)
__device__ float g_cs_wie[EN];    // sum_i w_ie[i][e] (ascending i)
__device__ float g_cs_wei[IN_];   // sum_e w_ei[e][i] (ascending e)

// ---------------- prep kernels (deterministic, rerun every launch) ----------------
__global__ void prep_pack(const float* __restrict__ wrec) {
    int idx = blockIdx.x * blockDim.x + threadIdx.x;  // 0 .. EN*EWORDS-1
    int j = idx >> 6, w = idx & 63;
    // w_rec entries are exactly 0.0f or 1.0f -> nonzero iff bit pattern nonzero
    const uint4* p = reinterpret_cast<const uint4*>(wrec + (size_t)j * EN + (size_t)w * 32);
    uint32_t m = 0;
#pragma unroll
    for (int k = 0; k < 8; k++) {
        uint4 f = p[k];
        m |= (f.x ? 1u : 0u) << (k * 4 + 0);
        m |= (f.y ? 1u : 0u) << (k * 4 + 1);
        m |= (f.z ? 1u : 0u) << (k * 4 + 2);
        m |= (f.w ? 1u : 0u) << (k * 4 + 3);
    }
    g_wrec_t[w * EN + j] = m;
}

__global__ void prep_sums(const float* __restrict__ wie, const float* __restrict__ wei) {
    int t = blockIdx.x * blockDim.x + threadIdx.x;  // 2048 threads
    if (t < EN) {
        int c = 0;
#pragma unroll 8
        for (int w = 0; w < EWORDS; w++) c += __popc(g_wrec_t[w * EN + t]);
        g_rowsum[t] = (float)c;
        float s = 0.f;
#pragma unroll 4
        for (int i = 0; i < IN_; i++) s = __fadd_rn(s, wie[(size_t)i * EN + t]);
        g_cs_wie[t] = s;
    }
    if (t < IN_) {
        float s = 0.f;
#pragma unroll 4
        for (int e = 0; e < EN; e++) s = __fadd_rn(s, wei[(size_t)e * IN_ + t]);
        g_cs_wei[t] = s;
    }
}

// ---------------- main simulator: one CTA per batch, fully independent ----------------
__global__ __launch_bounds__(NT, 1)
void sim_kernel(const float* __restrict__ x,
                const float* __restrict__ wei,
                const float* __restrict__ wie,
                float* __restrict__ out)
{
    __shared__ uint32_t s_ez[2][EWORDS];
    __shared__ uint32_t s_iz[2][IWORDS];
    __shared__ uint32_t s_flags[2];   // cnt_e | (cnt_i << 12)

    const int tid  = threadIdx.x;
    const int b    = blockIdx.x;
    const int warp = tid >> 5, lane = tid & 31;

    // register-resident state for the whole run (neurons tid + 512*j)
    float v[4]  = {0.f, 0.f, 0.f, 0.f};
    float cu[4] = {0.f, 0.f, 0.f, 0.f};
    float iv = 0.f, ii = 0.f;          // inh neuron tid (tid < 256)

    // loop-invariant constants hoisted to registers
    float rs[4], cw[4];
#pragma unroll
    for (int j = 0; j < 4; j++) {
        rs[j] = g_rowsum[tid + NT * j];
        cw[j] = g_cs_wie[tid + NT * j];
    }
    const float cwei = (tid < IN_) ? g_cs_wei[tid] : 0.f;

    if (tid < EWORDS) { s_ez[0][tid] = 0u; s_ez[1][tid] = 0u; }
    if (tid < IWORDS) { s_iz[0][tid] = 0u; s_iz[1][tid] = 0u; }
    __syncthreads();

    uint32_t pflags = 0;  // counts of previous step's spikes

    float xn[4];
#pragma unroll
    for (int j = 0; j < 4; j++) xn[j] = x[(size_t)b * EN + tid + NT * j];
    float* op = out + (size_t)b * EN;

    for (int t = 0; t < TN; t++) {
        const int wp = t & 1, rp = wp ^ 1;
        const int pce = (int)(pflags & 0xfffu);
        const int pci = (int)(pflags >> 12);

        // ---- [a] cross terms from previous step's spikes ----
        float rec[4], inh[4];
        if (pce == EN) {
#pragma unroll
            for (int j = 0; j < 4; j++) rec[j] = rs[j];
        } else if (pce == 0) {
#pragma unroll
            for (int j = 0; j < 4; j++) rec[j] = 0.f;
        } else {
            int c[4] = {0, 0, 0, 0};
#pragma unroll 8
            for (int w = 0; w < EWORDS; w++) {
                uint32_t ez = s_ez[rp][w];
#pragma unroll
                for (int j = 0; j < 4; j++)
                    c[j] += __popc(ez & g_wrec_t[w * EN + tid + NT * j]);
            }
#pragma unroll
            for (int j = 0; j < 4; j++) rec[j] = (float)c[j];
        }

        if (pci == IN_) {
#pragma unroll
            for (int j = 0; j < 4; j++) inh[j] = cw[j];
        } else if (pci == 0) {
#pragma unroll
            for (int j = 0; j < 4; j++) inh[j] = 0.f;
        } else {
            // fixed-trip predicated loop: serial exact fadd chain, loads fully pipelined
            uint4 ma = *reinterpret_cast<const uint4*>(&s_iz[rp][0]);
            uint4 mb = *reinterpret_cast<const uint4*>(&s_iz[rp][4]);
            uint32_t mw[8] = {ma.x, ma.y, ma.z, ma.w, mb.x, mb.y, mb.z, mb.w};
#pragma unroll
            for (int j = 0; j < 4; j++) inh[j] = 0.f;
#pragma unroll 2
            for (int w = 0; w < IWORDS; w++) {
                uint32_t m = mw[w];
#pragma unroll 8
                for (int k = 0; k < 32; k++) {
                    const float* wr = wie + (size_t)(w * 32 + k) * EN + tid;
                    float w0 = wr[0], w1 = wr[NT], w2 = wr[2 * NT], w3 = wr[3 * NT];
                    if ((m >> k) & 1u) {
                        inh[0] = __fadd_rn(inh[0], w0);
                        inh[1] = __fadd_rn(inh[1], w1);
                        inh[2] = __fadd_rn(inh[2], w2);
                        inh[3] = __fadd_rn(inh[3], w3);
                    }
                }
            }
        }

        // ---- [b] excitatory update (JAX-exact rounding order) ----
        int z[4];
#pragma unroll
        for (int j = 0; j < 4; j++) {
            float id = __fadd_rn(cu[j], __fmul_rn(-0.2f, cu[j]));
            float vd = __fadd_rn(v[j], __fmul_rn(0.1f, __fadd_rn(__fsub_rn(0.f, v[j]), cu[j])));
            z[j] = __fsub_rn(vd, 1.0f) > 0.f;
            v[j] = z[j] ? 0.f : vd;
            cu[j] = __fadd_rn(__fadd_rn(id, __fsub_rn(xn[j], inh[j])), rec[j]);
            op[tid + NT * j] = z[j] ? 1.f : 0.f;
        }
        op += (size_t)BN * EN;

        // prefetch next step's input (off the critical path)
        if (t + 1 < TN) {
            const float* xb = x + ((size_t)(t + 1) * BN + b) * EN;
#pragma unroll
            for (int j = 0; j < 4; j++) xn[j] = xb[tid + NT * j];
        }

        // inhibitory decay + spike from OLD inh state (no dep on new ez)
        float ii_dec = __fadd_rn(ii, __fmul_rn(-0.2f, ii));
        float vi_dec = __fadd_rn(iv, __fmul_rn(0.1f, __fadd_rn(__fsub_rn(0.f, iv), ii)));
        int zi = __fsub_rn(vi_dec, 1.0f) > 0.f;   // tid>=256: state stays 0 -> zi=0
        iv = zi ? 0.f : vi_dec;

        // ---- [c] publish new spikes (ballots only, no atomics) ----
        uint32_t eb0 = __ballot_sync(0xffffffffu, z[0]);
        uint32_t eb1 = __ballot_sync(0xffffffffu, z[1]);
        uint32_t eb2 = __ballot_sync(0xffffffffu, z[2]);
        uint32_t eb3 = __ballot_sync(0xffffffffu, z[3]);
        uint32_t ibal = __ballot_sync(0xffffffffu, zi);
        if (lane == 0) {
            s_ez[wp][warp]      = eb0;
            s_ez[wp][16 + warp] = eb1;
            s_ez[wp][32 + warp] = eb2;
            s_ez[wp][48 + warp] = eb3;
            if (warp < IWORDS) s_iz[wp][warp] = ibal;
        }
        __syncthreads();  // sync1: publication visible

        // ---- aggregator: warp 0 computes spike counts, one smem word ----
        if (warp == 0) {
            uint32_t w0 = s_ez[wp][2 * lane], w1 = s_ez[wp][2 * lane + 1];
            int ce = __popc(w0) + __popc(w1);
            int ci = (lane < IWORDS) ? __popc(s_iz[wp][lane]) : 0;
#pragma unroll
            for (int off = 16; off > 0; off >>= 1) {
                ce += __shfl_down_sync(0xffffffffu, ce, off);
                ci += __shfl_down_sync(0xffffffffu, ci, off);
            }
            if (lane == 0) s_flags[wp] = (uint32_t)ce | ((uint32_t)ci << 12);
        }
        __syncthreads();  // sync2: flags visible

        uint32_t nflags = s_flags[wp];

        // ---- [d] inhibitory current update with NEW exc spikes ----
        if (tid < IN_) {
            int nce = (int)(nflags & 0xfffu);
            float xi;
            if (nce == EN)      xi = cwei;
            else if (nce == 0)  xi = 0.f;
            else if (nce <= 96) {
                // sparse: bit-scan, ascending order
                xi = 0.f;
                for (int w = 0; w < EWORDS; w++) {
                    uint32_t m = s_ez[wp][w];
                    while (m) {
                        int c = __ffs(m) - 1; m &= m - 1;
                        xi = __fadd_rn(xi, wei[(size_t)(w * 32 + c) * IN_ + tid]);
                    }
                }
            } else {
                // dense: fixed-trip predicated, loads pipelined, exact ascending chain
                xi = 0.f;
                for (int w = 0; w < EWORDS; w++) {
                    uint32_t m = s_ez[wp][w];
#pragma unroll 8
                    for (int k = 0; k < 32; k++) {
                        float wv = wei[(size_t)(w * 32 + k) * IN_ + tid];
                        if ((m >> k) & 1u) xi = __fadd_rn(xi, wv);
                    }
                }
            }
            ii = __fadd_rn(ii_dec, xi);
        }
        pflags = nflags;
        // next iteration writes buffer rp: its last readers were this step's [a]
        // (before sync1) -> ordered. flags[rp] last read one step ago -> ordered.
    }
}

extern "C" void kernel_launch(void* const* d_in, const int* in_sizes, int n_in,
                              void* d_out, int out_size)
{
    const float* x     = (const float*)d_in[0];  // [T,B,E]
    // d_in[1] = w_in (identity) -- exact pass-through, unused
    const float* w_rec = (const float*)d_in[2];  // [E,E]
    const float* w_ei  = (const float*)d_in[3];  // [E,I]
    const float* w_ie  = (const float*)d_in[4];  // [I,E]
    float* out = (float*)d_out;

    prep_pack<<<(EN * EWORDS) / 256, 256>>>(w_rec);
    prep_sums<<<8, 256>>>(w_ie, w_ei);
    sim_kernel<<<BN, NT>>>(x, w_ei, w_ie, out);
}